// round 16
// baseline (speedup 1.0000x reference)
#include <cuda_runtime.h>
#include <cstdint>
#include <cstddef>

// Problem: B=4, S=2048 -> TOK=8192 tokens, D=512, E=32, F=512
#define TOK   8192
#define DDIM  512
#define NEXP  32

// -------------------- device scratch --------------------
__device__ float g_gate[TOK * NEXP];   // softmax gates [t][e]
// Fragment-packed fp16 W for mma.m16n8k16:
// u32 chunks: [fb 4][dc 16][ks2 2][e 32] -> chunk of 1024 u32:
//   [wn 4][l 2][lane 32][r 4],  u32 = {lo=W[k][f], hi=W[k+1][f]}
__device__ uint32_t g_wt2h[4 * 16 * 2 * 32 * 1024 + 4096];   // 16.8MB + 16KB pad

// -------------------- helpers --------------------
__device__ __forceinline__ uint32_t smem_u32(const void* p) {
    uint32_t a;
    asm("{ .reg .u64 t; cvta.to.shared.u64 t, %1; cvt.u32.u64 %0, t; }"
        : "=r"(a) : "l"(p));
    return a;
}
// pack two f32 -> f16x2 {lo, hi}  (first asm operand = hi half)
__device__ __forceinline__ uint32_t packh2(float lo, float hi) {
    uint32_t d;
    asm("cvt.rn.f16x2.f32 %0, %1, %2;" : "=r"(d) : "f"(hi), "f"(lo));
    return d;
}
__device__ __forceinline__ uint32_t hmul2(uint32_t a, uint32_t b) {
    uint32_t d;
    asm("mul.f16x2 %0, %1, %2;" : "=r"(d) : "r"(a), "r"(b));
    return d;
}
// fp32-accumulate MMA
__device__ __forceinline__ void mma_f16(float* c, uint32_t a0, uint32_t a1,
                                        uint32_t a2, uint32_t a3,
                                        uint32_t b0, uint32_t b1) {
    asm volatile(
        "mma.sync.aligned.m16n8k16.row.col.f32.f16.f16.f32 "
        "{%0,%1,%2,%3}, {%4,%5,%6,%7}, {%8,%9}, {%0,%1,%2,%3};"
        : "+f"(c[0]), "+f"(c[1]), "+f"(c[2]), "+f"(c[3])
        : "r"(a0), "r"(a1), "r"(a2), "r"(a3), "r"(b0), "r"(b1));
}

// ============ Kernel 1: fused prepass (W repack) + tensor-core gate ==========
#define PRE_SMEM (32 * 516 * 4)   // 66048

__global__ void __launch_bounds__(256) prep_gate_kernel(
    const float* __restrict__ ew, const float* __restrict__ x,
    const float* __restrict__ gw, const float* __restrict__ gbias)
{
    extern __shared__ float ws[];
    int tid = threadIdx.x;
    int bid = blockIdx.x;

    if (bid < 512) {
        int e = bid & 31, dc = bid >> 5;
        const float4* src = reinterpret_cast<const float4*>(
            ew + ((size_t)e * DDIM + dc * 32) * DDIM);
        #pragma unroll
        for (int m = 0; m < 16; m++) {
            int v = tid + 256 * m;
            int kk = v >> 7, fq = v & 127;
            float4 tv = src[v];
            *reinterpret_cast<float4*>(ws + kk * 516 + fq * 4) = tv;
        }
        __syncthreads();

        #pragma unroll
        for (int m = 0; m < 8; m++) {
            int v = tid + 256 * m;
            int lane = v & 31;
            int l    = (v >> 5) & 1;
            int wn   = (v >> 6) & 3;
            int ks2  = (v >> 8) & 1;
            int fb   = (v >> 9) & 3;
            int tig = lane & 3, gid = lane >> 2;
            uint32_t o[4];
            #pragma unroll
            for (int r = 0; r < 4; r++) {
                int k = ks2 * 16 + 2 * tig + (r & 1) * 8;
                int f = fb * 128 + wn * 32 + (l * 2 + (r >> 1)) * 8 + gid;
                o[r] = packh2(ws[k * 516 + f], ws[(k + 1) * 516 + f]);
            }
            size_t idx4 = ((((size_t)(fb * 16 + dc) * 2 + ks2) * 32 + e) * 256)
                        + wn * 64 + l * 32 + lane;
            reinterpret_cast<uint4*>(g_wt2h)[idx4] =
                make_uint4(o[0], o[1], o[2], o[3]);
        }
    } else {
        uint32_t* xsu  = reinterpret_cast<uint32_t*>(ws);
        uint32_t* gwsu = reinterpret_cast<uint32_t*>(ws) + 128*20;
        int t0 = (bid - 512) * 128;
        int lane = tid & 31, w = tid >> 5;
        int tig = lane & 3, gid = lane >> 2;

        float acc[4][4];
        #pragma unroll
        for (int j = 0; j < 4; j++)
            #pragma unroll
            for (int q = 0; q < 4; q++) acc[j][q] = 0.f;

        #pragma unroll 1
        for (int dc = 0; dc < 16; dc++) {
            __syncthreads();
            #pragma unroll
            for (int m = 0; m < 4; m++) {
                int u = tid + 256 * m;
                int row = u >> 3, c4 = u & 7;
                float4 v = *reinterpret_cast<const float4*>(
                    x + (size_t)(t0 + row) * DDIM + dc * 32 + c4 * 4);
                xsu[row * 20 + c4 * 2]     = packh2(v.x, v.y);
                xsu[row * 20 + c4 * 2 + 1] = packh2(v.z, v.w);
            }
            {
                int kp = tid >> 4;
                int e2 = (tid & 15) * 2;
                float2 w0 = *reinterpret_cast<const float2*>(
                    gw + (size_t)(dc * 32 + 2 * kp) * NEXP + e2);
                float2 w1 = *reinterpret_cast<const float2*>(
                    gw + (size_t)(dc * 32 + 2 * kp + 1) * NEXP + e2);
                gwsu[kp * 36 + e2]     = packh2(w0.x, w1.x);
                gwsu[kp * 36 + e2 + 1] = packh2(w0.y, w1.y);
            }
            __syncthreads();

            #pragma unroll
            for (int kq = 0; kq < 2; kq++) {
                int kpb = kq * 8 + tig;
                uint32_t a0 = xsu[(w * 16 + gid) * 20 + kpb];
                uint32_t a1 = xsu[(w * 16 + gid + 8) * 20 + kpb];
                uint32_t a2 = xsu[(w * 16 + gid) * 20 + kpb + 4];
                uint32_t a3 = xsu[(w * 16 + gid + 8) * 20 + kpb + 4];
                #pragma unroll
                for (int j = 0; j < 4; j++) {
                    uint32_t b0 = gwsu[kpb * 36 + j * 8 + gid];
                    uint32_t b1 = gwsu[(kpb + 4) * 36 + j * 8 + gid];
                    mma_f16(acc[j], a0, a1, a2, a3, b0, b1);
                }
            }
        }

        float lr0[8], lr1[8];
        #pragma unroll
        for (int j = 0; j < 4; j++) {
            int c0 = j * 8 + tig * 2;
            float b0 = __ldg(gbias + c0), b1 = __ldg(gbias + c0 + 1);
            lr0[j * 2]     = acc[j][0] + b0;
            lr0[j * 2 + 1] = acc[j][1] + b1;
            lr1[j * 2]     = acc[j][2] + b0;
            lr1[j * 2 + 1] = acc[j][3] + b1;
        }
        float m0 = lr0[0], m1 = lr1[0];
        #pragma unroll
        for (int q = 1; q < 8; q++) {
            m0 = fmaxf(m0, lr0[q]); m1 = fmaxf(m1, lr1[q]);
        }
        #pragma unroll
        for (int o = 1; o <= 2; o <<= 1) {
            m0 = fmaxf(m0, __shfl_xor_sync(0xFFFFFFFFu, m0, o));
            m1 = fmaxf(m1, __shfl_xor_sync(0xFFFFFFFFu, m1, o));
        }
        float s0 = 0.f, s1 = 0.f;
        #pragma unroll
        for (int q = 0; q < 8; q++) {
            lr0[q] = __expf(lr0[q] - m0); s0 += lr0[q];
            lr1[q] = __expf(lr1[q] - m1); s1 += lr1[q];
        }
        #pragma unroll
        for (int o = 1; o <= 2; o <<= 1) {
            s0 += __shfl_xor_sync(0xFFFFFFFFu, s0, o);
            s1 += __shfl_xor_sync(0xFFFFFFFFu, s1, o);
        }
        float i0 = 1.0f / s0, i1 = 1.0f / s1;
        int r0 = t0 + w * 16 + gid;
        #pragma unroll
        for (int j = 0; j < 4; j++) {
            int c0 = j * 8 + tig * 2;
            *reinterpret_cast<float2*>(g_gate + (size_t)r0 * NEXP + c0) =
                make_float2(lr0[j * 2] * i0, lr0[j * 2 + 1] * i0);
            *reinterpret_cast<float2*>(g_gate + (size_t)(r0 + 8) * NEXP + c0) =
                make_float2(lr1[j * 2] * i1, lr1[j * 2 + 1] * i1);
        }
    }
}

// ======================== Kernel 2: main fp16 HMMA GEMM ======================
// grid (4 fblk, 64 tblk) = 256 CTAs of 128 threads, occ 2.
// 4 warps as 2(M) x 2(N); warp tile 64M x 64N (R15's winning shape).
// NEW vs R15: prefetch.global.L1 of chunk t+2 — register-free distance-2 B
// pipeline. Each thread prefetches its own 4 slot addresses one chunk beyond
// the register prefetch, converting next-next-iter L2 misses into L1 hits.
#define MAIN_SMEM ((128 * 20 + 128 * 36) * 4)   // 28672

#define LDB4(b0, b1, b2, b3, p) do {                                   \
    (b0) = *reinterpret_cast<const uint4*>(p);                         \
    (b1) = *reinterpret_cast<const uint4*>((p) + 128);                 \
    (b2) = *reinterpret_cast<const uint4*>((p) + 256);                 \
    (b3) = *reinterpret_cast<const uint4*>((p) + 384);                 \
} while (0)

#define PREF4(p) do {                                                  \
    asm volatile("prefetch.global.L1 [%0];" :: "l"(p));                \
    asm volatile("prefetch.global.L1 [%0];" :: "l"((p) + 128));        \
    asm volatile("prefetch.global.L1 [%0];" :: "l"((p) + 256));        \
    asm volatile("prefetch.global.L1 [%0];" :: "l"((p) + 384));        \
} while (0)

// 32-MMA block (4 m-fragments x 8 n-tiles) using pre-loaded gates gpe[i][h][u]
#define MMABLOCK_R(u, q0, q1, q2, q3) do {                             \
    _Pragma("unroll")                                                  \
    for (int i = 0; i < 4; i++) {                                      \
        uint32_t a0 = hmul2(gpe[i][0][u], xh[i][0]);                   \
        uint32_t a1 = hmul2(gpe[i][1][u], xh[i][1]);                   \
        uint32_t a2 = hmul2(gpe[i][0][u], xh[i][2]);                   \
        uint32_t a3 = hmul2(gpe[i][1][u], xh[i][3]);                   \
        mma_f16(acc[i][0], a0, a1, a2, a3, (q0).x, (q0).y);            \
        mma_f16(acc[i][1], a0, a1, a2, a3, (q0).z, (q0).w);            \
        mma_f16(acc[i][2], a0, a1, a2, a3, (q1).x, (q1).y);            \
        mma_f16(acc[i][3], a0, a1, a2, a3, (q1).z, (q1).w);            \
        mma_f16(acc[i][4], a0, a1, a2, a3, (q2).x, (q2).y);            \
        mma_f16(acc[i][5], a0, a1, a2, a3, (q2).z, (q2).w);            \
        mma_f16(acc[i][6], a0, a1, a2, a3, (q3).x, (q3).y);            \
        mma_f16(acc[i][7], a0, a1, a2, a3, (q3).z, (q3).w);            \
    }                                                                  \
} while (0)

__global__ void __launch_bounds__(128, 2) moe_main_kernel(
    const float* __restrict__ x, float* __restrict__ out)
{
    extern __shared__ uint32_t smu[];
    uint32_t* xsu = smu;               // [128][20]
    uint32_t* ghu = smu + 128 * 20;    // [128][36]
    uint32_t xcA = smem_u32(xsu);
    uint32_t ghA_base = xcA + 128u * 20u * 4u;

    int tid = threadIdx.x, lane = tid & 31, wid = tid >> 5;
    int wm = wid >> 1;              // 0..1 -> 64 rows each
    int wn = wid & 1;               // 0..1 -> 64 cols each
    int fblk = blockIdx.x;
    int t0 = blockIdx.y * 128;
    int f0 = fblk * 128;
    int tig = lane & 3, gid = lane >> 2;

    // ---- stage gate tile as replicated fp16x2 {g,g} (128 rows) ----
    #pragma unroll
    for (int m = 0; m < 8; m++) {
        int u = tid + 128 * m;      // 1024 float4
        int row = u >> 3, wq = u & 7;
        float4 v = *reinterpret_cast<const float4*>(
            g_gate + (size_t)(t0 + row) * NEXP + wq * 4);
        ghu[row * 36 + wq * 4 + 0] = packh2(v.x, v.x);
        ghu[row * 36 + wq * 4 + 1] = packh2(v.y, v.y);
        ghu[row * 36 + wq * 4 + 2] = packh2(v.z, v.z);
        ghu[row * 36 + wq * 4 + 3] = packh2(v.w, v.w);
    }

    // ---- B stream: linear chunk order [dc][ks2][e], 1024 chunks ----
    const uint32_t* pB = g_wt2h + (size_t)fblk * (16 * 2 * 32 * 1024)
                       + (wn * 128 + lane) * 4;
    uint4 bc0, bc1, bc2, bc3, bn0, bn1, bn2, bn3;
    LDB4(bc0, bc1, bc2, bc3, pB);   // chunk 0
    pB += 1024;
    PREF4(pB);                       // warm chunk 1 lines

    float acc[4][8][4];
    #pragma unroll
    for (int i = 0; i < 4; i++)
        #pragma unroll
        for (int j = 0; j < 8; j++)
            #pragma unroll
            for (int q = 0; q < 4; q++) acc[i][j][q] = 0.f;

    uint32_t xh[4][4];
    uint32_t gA = ghA_base + (uint32_t)(wm * 64 + gid) * 144u;

    #pragma unroll 1
    for (int dc = 0; dc < 16; dc++) {
        __syncthreads();
        // stage x chunk as fp16x2 pairs (128 rows)
        #pragma unroll
        for (int m = 0; m < 8; m++) {
            int u = tid + 128 * m;      // 1024 float4
            int row = u >> 3, c4 = u & 7;
            float4 v = *reinterpret_cast<const float4*>(
                x + (size_t)(t0 + row) * DDIM + dc * 32 + c4 * 4);
            xsu[row * 20 + c4 * 2]     = packh2(v.x, v.y);
            xsu[row * 20 + c4 * 2 + 1] = packh2(v.z, v.w);
        }
        __syncthreads();

        #pragma unroll 1
        for (int ks2 = 0; ks2 < 2; ks2++) {
            // hoisted x-fragment loads (conflict-free banks)
            #pragma unroll
            for (int i = 0; i < 4; i++) {
                uint32_t base = xcA
                    + ((uint32_t)(wm * 64 + 16 * i + gid) * 20u
                       + (uint32_t)(ks2 * 8 + tig)) * 4u;
                asm("ld.shared.b32 %0, [%1];" : "=r"(xh[i][0]) : "r"(base));
                asm("ld.shared.b32 %0, [%1];" : "=r"(xh[i][1]) : "r"(base + 8u*20u*4u));
                asm("ld.shared.b32 %0, [%1];" : "=r"(xh[i][2]) : "r"(base + 16u));
                asm("ld.shared.b32 %0, [%1];" : "=r"(xh[i][3]) : "r"(base + 8u*20u*4u + 16u));
            }

            // e-unrolled x2; register buffer = distance 1, L1 prefetch =
            // distance 2. Final prefetch/fetch overruns land in the 16KB pad.
            #pragma unroll 1
            for (int ep = 0; ep < 16; ep++) {
                uint32_t gpe[4][2][2];   // [i][row-half][u]
                #pragma unroll
                for (int i = 0; i < 4; i++) {
                    asm("ld.shared.v2.b32 {%0,%1}, [%2];"
                        : "=r"(gpe[i][0][0]), "=r"(gpe[i][0][1])
                        : "r"(gA + (uint32_t)(i * 2304) + (uint32_t)(ep * 8)));
                    asm("ld.shared.v2.b32 {%0,%1}, [%2];"
                        : "=r"(gpe[i][1][0]), "=r"(gpe[i][1][1])
                        : "r"(gA + (uint32_t)(i * 2304 + 1152) + (uint32_t)(ep * 8)));
                }
                // e = 2*ep: fetch next into bn* (L1-warmed), consume bc*
                LDB4(bn0, bn1, bn2, bn3, pB); pB += 1024;
                PREF4(pB);               // warm chunk t+2
                MMABLOCK_R(0, bc0, bc1, bc2, bc3);
                // e = 2*ep+1: fetch next into bc*, consume bn*
                LDB4(bc0, bc1, bc2, bc3, pB); pB += 1024;
                PREF4(pB);               // warm chunk t+2
                MMABLOCK_R(1, bn0, bn1, bn2, bn3);
            }
        }
    }

    // ---- epilogue ----
    #pragma unroll
    for (int i = 0; i < 4; i++) {
        int row = t0 + wm * 64 + 16 * i + gid;
        #pragma unroll
        for (int j = 0; j < 8; j++) {
            int col = f0 + wn * 64 + 8 * j + 2 * tig;
            *reinterpret_cast<float2*>(out + (size_t)row * DDIM + col) =
                make_float2(acc[i][j][0], acc[i][j][1]);
            *reinterpret_cast<float2*>(out + (size_t)(row + 8) * DDIM + col) =
                make_float2(acc[i][j][2], acc[i][j][3]);
        }
    }
}

// ======================== launch ========================
extern "C" void kernel_launch(void* const* d_in, const int* in_sizes, int n_in,
                              void* d_out, int out_size) {
    const float* x  = (const float*)d_in[0];   // [8192, 512]
    const float* gw = (const float*)d_in[1];   // [512, 32]
    const float* gb = (const float*)d_in[2];   // [32]
    const float* ew = (const float*)d_in[3];   // [32, 512, 512]
    float* out = (float*)d_out;                // [8192, 512]

    cudaFuncSetAttribute(prep_gate_kernel,
                         cudaFuncAttributeMaxDynamicSharedMemorySize, PRE_SMEM);
    cudaFuncSetAttribute(moe_main_kernel,
                         cudaFuncAttributeMaxDynamicSharedMemorySize, MAIN_SMEM);

    prep_gate_kernel<<<576, 256, PRE_SMEM>>>(ew, x, gw, gb);

    dim3 grid(4, 64);
    moe_main_kernel<<<grid, 128, MAIN_SMEM>>>(x, out);
}

// round 17
// speedup vs baseline: 1.0420x; 1.0420x over previous
#include <cuda_runtime.h>
#include <cstdint>
#include <cstddef>

// Problem: B=4, S=2048 -> TOK=8192 tokens, D=512, E=32, F=512
#define TOK   8192
#define DDIM  512
#define NEXP  32

// -------------------- device scratch --------------------
__device__ float g_gate[TOK * NEXP];   // softmax gates [t][e]
// Fragment-packed fp16 W for mma.m16n8k16 (see R5..R16 layout comment)
__device__ uint32_t g_wt2h[4 * 16 * 2 * 32 * 1024 + 4096];   // 16.8MB + pad
// Pre-converted fp16x2 x tiles in main-kernel smem layout:
// [tblk 64][dc 16][row 128][kp 16] u32  (8MB)
__device__ uint32_t g_xh[(size_t)64 * 16 * 128 * 16];

// -------------------- helpers --------------------
__device__ __forceinline__ uint32_t smem_u32(const void* p) {
    uint32_t a;
    asm("{ .reg .u64 t; cvta.to.shared.u64 t, %1; cvt.u32.u64 %0, t; }"
        : "=r"(a) : "l"(p));
    return a;
}
// pack two f32 -> f16x2 {lo, hi}  (first asm operand = hi half)
__device__ __forceinline__ uint32_t packh2(float lo, float hi) {
    uint32_t d;
    asm("cvt.rn.f16x2.f32 %0, %1, %2;" : "=r"(d) : "f"(hi), "f"(lo));
    return d;
}
__device__ __forceinline__ uint32_t hmul2(uint32_t a, uint32_t b) {
    uint32_t d;
    asm("mul.f16x2 %0, %1, %2;" : "=r"(d) : "r"(a), "r"(b));
    return d;
}
// fp32-accumulate MMA
__device__ __forceinline__ void mma_f16(float* c, uint32_t a0, uint32_t a1,
                                        uint32_t a2, uint32_t a3,
                                        uint32_t b0, uint32_t b1) {
    asm volatile(
        "mma.sync.aligned.m16n8k16.row.col.f32.f16.f16.f32 "
        "{%0,%1,%2,%3}, {%4,%5,%6,%7}, {%8,%9}, {%0,%1,%2,%3};"
        : "+f"(c[0]), "+f"(c[1]), "+f"(c[2]), "+f"(c[3])
        : "r"(a0), "r"(a1), "r"(a2), "r"(a3), "r"(b0), "r"(b1));
}
#define CPA16(dst, src) \
    asm volatile("cp.async.ca.shared.global [%0], [%1], 16;" \
        :: "r"(dst), "l"(src) : "memory")
#define CP_COMMIT() asm volatile("cp.async.commit_group;" ::: "memory")
#define CP_WAIT1()  asm volatile("cp.async.wait_group 1;" ::: "memory")
#define CP_WAIT0()  asm volatile("cp.async.wait_group 0;" ::: "memory")

// ==== Kernel 1: fused prepass (W repack + x fp16 convert) + TC gate ==========
// Blocks 0..511: W repack (e = bid & 31, dc = bid >> 5).
// Blocks 512..575: gate for tokens [(bid-512)*128, +128).
// Blocks 576..703: x fp16 convert, 64 tokens per block.
#define PRE_SMEM (32 * 516 * 4)   // 66048

__global__ void __launch_bounds__(256) prep_gate_kernel(
    const float* __restrict__ ew, const float* __restrict__ x,
    const float* __restrict__ gw, const float* __restrict__ gbias)
{
    extern __shared__ float ws[];
    int tid = threadIdx.x;
    int bid = blockIdx.x;

    if (bid < 512) {
        // ---------------- W repack to fragment-packed fp16 ----------------
        int e = bid & 31, dc = bid >> 5;
        const float4* src = reinterpret_cast<const float4*>(
            ew + ((size_t)e * DDIM + dc * 32) * DDIM);
        #pragma unroll
        for (int m = 0; m < 16; m++) {
            int v = tid + 256 * m;
            int kk = v >> 7, fq = v & 127;
            float4 tv = src[v];
            *reinterpret_cast<float4*>(ws + kk * 516 + fq * 4) = tv;
        }
        __syncthreads();

        #pragma unroll
        for (int m = 0; m < 8; m++) {
            int v = tid + 256 * m;
            int lane = v & 31;
            int l    = (v >> 5) & 1;
            int wn   = (v >> 6) & 3;
            int ks2  = (v >> 8) & 1;
            int fb   = (v >> 9) & 3;
            int tig = lane & 3, gid = lane >> 2;
            uint32_t o[4];
            #pragma unroll
            for (int r = 0; r < 4; r++) {
                int k = ks2 * 16 + 2 * tig + (r & 1) * 8;
                int f = fb * 128 + wn * 32 + (l * 2 + (r >> 1)) * 8 + gid;
                o[r] = packh2(ws[k * 516 + f], ws[(k + 1) * 516 + f]);
            }
            size_t idx4 = ((((size_t)(fb * 16 + dc) * 2 + ks2) * 32 + e) * 256)
                        + wn * 64 + l * 32 + lane;
            reinterpret_cast<uint4*>(g_wt2h)[idx4] =
                make_uint4(o[0], o[1], o[2], o[3]);
        }
    } else if (bid < 576) {
        // ---------------- gate: fp16 MMA GEMM + softmax ----------------
        uint32_t* xsu  = reinterpret_cast<uint32_t*>(ws);
        uint32_t* gwsu = reinterpret_cast<uint32_t*>(ws) + 128*20;
        int t0 = (bid - 512) * 128;
        int lane = tid & 31, w = tid >> 5;
        int tig = lane & 3, gid = lane >> 2;

        float acc[4][4];
        #pragma unroll
        for (int j = 0; j < 4; j++)
            #pragma unroll
            for (int q = 0; q < 4; q++) acc[j][q] = 0.f;

        #pragma unroll 1
        for (int dc = 0; dc < 16; dc++) {
            __syncthreads();
            #pragma unroll
            for (int m = 0; m < 4; m++) {
                int u = tid + 256 * m;
                int row = u >> 3, c4 = u & 7;
                float4 v = *reinterpret_cast<const float4*>(
                    x + (size_t)(t0 + row) * DDIM + dc * 32 + c4 * 4);
                xsu[row * 20 + c4 * 2]     = packh2(v.x, v.y);
                xsu[row * 20 + c4 * 2 + 1] = packh2(v.z, v.w);
            }
            {
                int kp = tid >> 4;
                int e2 = (tid & 15) * 2;
                float2 w0 = *reinterpret_cast<const float2*>(
                    gw + (size_t)(dc * 32 + 2 * kp) * NEXP + e2);
                float2 w1 = *reinterpret_cast<const float2*>(
                    gw + (size_t)(dc * 32 + 2 * kp + 1) * NEXP + e2);
                gwsu[kp * 36 + e2]     = packh2(w0.x, w1.x);
                gwsu[kp * 36 + e2 + 1] = packh2(w0.y, w1.y);
            }
            __syncthreads();

            #pragma unroll
            for (int kq = 0; kq < 2; kq++) {
                int kpb = kq * 8 + tig;
                uint32_t a0 = xsu[(w * 16 + gid) * 20 + kpb];
                uint32_t a1 = xsu[(w * 16 + gid + 8) * 20 + kpb];
                uint32_t a2 = xsu[(w * 16 + gid) * 20 + kpb + 4];
                uint32_t a3 = xsu[(w * 16 + gid + 8) * 20 + kpb + 4];
                #pragma unroll
                for (int j = 0; j < 4; j++) {
                    uint32_t b0 = gwsu[kpb * 36 + j * 8 + gid];
                    uint32_t b1 = gwsu[(kpb + 4) * 36 + j * 8 + gid];
                    mma_f16(acc[j], a0, a1, a2, a3, b0, b1);
                }
            }
        }

        float lr0[8], lr1[8];
        #pragma unroll
        for (int j = 0; j < 4; j++) {
            int c0 = j * 8 + tig * 2;
            float b0 = __ldg(gbias + c0), b1 = __ldg(gbias + c0 + 1);
            lr0[j * 2]     = acc[j][0] + b0;
            lr0[j * 2 + 1] = acc[j][1] + b1;
            lr1[j * 2]     = acc[j][2] + b0;
            lr1[j * 2 + 1] = acc[j][3] + b1;
        }
        float m0 = lr0[0], m1 = lr1[0];
        #pragma unroll
        for (int q = 1; q < 8; q++) {
            m0 = fmaxf(m0, lr0[q]); m1 = fmaxf(m1, lr1[q]);
        }
        #pragma unroll
        for (int o = 1; o <= 2; o <<= 1) {
            m0 = fmaxf(m0, __shfl_xor_sync(0xFFFFFFFFu, m0, o));
            m1 = fmaxf(m1, __shfl_xor_sync(0xFFFFFFFFu, m1, o));
        }
        float s0 = 0.f, s1 = 0.f;
        #pragma unroll
        for (int q = 0; q < 8; q++) {
            lr0[q] = __expf(lr0[q] - m0); s0 += lr0[q];
            lr1[q] = __expf(lr1[q] - m1); s1 += lr1[q];
        }
        #pragma unroll
        for (int o = 1; o <= 2; o <<= 1) {
            s0 += __shfl_xor_sync(0xFFFFFFFFu, s0, o);
            s1 += __shfl_xor_sync(0xFFFFFFFFu, s1, o);
        }
        float i0 = 1.0f / s0, i1 = 1.0f / s1;
        int r0 = t0 + w * 16 + gid;
        #pragma unroll
        for (int j = 0; j < 4; j++) {
            int c0 = j * 8 + tig * 2;
            *reinterpret_cast<float2*>(g_gate + (size_t)r0 * NEXP + c0) =
                make_float2(lr0[j * 2] * i0, lr0[j * 2 + 1] * i0);
            *reinterpret_cast<float2*>(g_gate + (size_t)(r0 + 8) * NEXP + c0) =
                make_float2(lr1[j * 2] * i1, lr1[j * 2 + 1] * i1);
        }
    } else {
        // ------------- x fp16 convert: 64 tokens per block -------------
        int xb = bid - 576;              // 0..127
        int tblk = xb >> 1;
        int rowbase = (xb & 1) * 64;
        int t0x = tblk * 128 + rowbase;
        const float4* xsrc = reinterpret_cast<const float4*>(x)
                           + (size_t)t0x * (DDIM / 4);
        uint32_t* dstb = g_xh + (size_t)tblk * (16 * 2048);
        #pragma unroll
        for (int m = 0; m < 32; m++) {
            int u = tid + 256 * m;       // 8192 float4
            int dc = u >> 9;
            int v = u & 511;
            int row64 = v >> 3, c4 = v & 7;
            float4 t = xsrc[(size_t)row64 * (DDIM / 4) + dc * 8 + c4];
            size_t di = ((size_t)dc * 128 + rowbase + row64) * 16 + c4 * 2;
            dstb[di]     = packh2(t.x, t.y);
            dstb[di + 1] = packh2(t.z, t.w);
        }
    }
}

// ======================== Kernel 2: main fp16 HMMA GEMM ======================
// grid (4 fblk, 64 tblk) = 256 CTAs of 128 threads, occ 2.
// 4 warps as 2(M) x 2(N); warp tile 64M x 64N (R15's winning shape).
// NEW vs R15: x-staging via double-buffered cp.async from pre-converted
// g_xh tiles (no f32 loads, no converts, no exposed barrier latency).
#define XBUF_BYTES (128 * 20 * 4)   // 10240 per buffer
#define MAIN_SMEM (2 * XBUF_BYTES + 128 * 36 * 4)   // 38912

#define LDB4(b0, b1, b2, b3, p) do {                                   \
    (b0) = *reinterpret_cast<const uint4*>(p);                         \
    (b1) = *reinterpret_cast<const uint4*>((p) + 128);                 \
    (b2) = *reinterpret_cast<const uint4*>((p) + 256);                 \
    (b3) = *reinterpret_cast<const uint4*>((p) + 384);                 \
} while (0)

// 32-MMA block (4 m-fragments x 8 n-tiles) using pre-loaded gates gpe[i][h][u]
#define MMABLOCK_R(u, q0, q1, q2, q3) do {                             \
    _Pragma("unroll")                                                  \
    for (int i = 0; i < 4; i++) {                                      \
        uint32_t a0 = hmul2(gpe[i][0][u], xh[i][0]);                   \
        uint32_t a1 = hmul2(gpe[i][1][u], xh[i][1]);                   \
        uint32_t a2 = hmul2(gpe[i][0][u], xh[i][2]);                   \
        uint32_t a3 = hmul2(gpe[i][1][u], xh[i][3]);                   \
        mma_f16(acc[i][0], a0, a1, a2, a3, (q0).x, (q0).y);            \
        mma_f16(acc[i][1], a0, a1, a2, a3, (q0).z, (q0).w);            \
        mma_f16(acc[i][2], a0, a1, a2, a3, (q1).x, (q1).y);            \
        mma_f16(acc[i][3], a0, a1, a2, a3, (q1).z, (q1).w);            \
        mma_f16(acc[i][4], a0, a1, a2, a3, (q2).x, (q2).y);            \
        mma_f16(acc[i][5], a0, a1, a2, a3, (q2).z, (q2).w);            \
        mma_f16(acc[i][6], a0, a1, a2, a3, (q3).x, (q3).y);            \
        mma_f16(acc[i][7], a0, a1, a2, a3, (q3).z, (q3).w);            \
    }                                                                  \
} while (0)

__global__ void __launch_bounds__(128, 2) moe_main_kernel(
    float* __restrict__ out)
{
    extern __shared__ uint32_t smu[];
    uint32_t xcA0 = smem_u32(smu);                 // x buffer 0: [128][20]
    uint32_t xcA1 = xcA0 + XBUF_BYTES;             // x buffer 1
    uint32_t ghA_base = xcA0 + 2u * XBUF_BYTES;    // gates: [128][36]
    uint32_t* ghu = smu + 2 * (128 * 20);

    int tid = threadIdx.x, lane = tid & 31, wid = tid >> 5;
    int wm = wid >> 1;              // 0..1 -> 64 rows each
    int wn = wid & 1;               // 0..1 -> 64 cols each
    int fblk = blockIdx.x;
    int tblk = blockIdx.y;
    int t0 = tblk * 128;
    int f0 = fblk * 128;
    int tig = lane & 3, gid = lane >> 2;

    // ---- stage gate tile as replicated fp16x2 {g,g} (128 rows) ----
    #pragma unroll
    for (int m = 0; m < 8; m++) {
        int u = tid + 128 * m;      // 1024 float4
        int row = u >> 3, wq = u & 7;
        float4 v = *reinterpret_cast<const float4*>(
            g_gate + (size_t)(t0 + row) * NEXP + wq * 4);
        ghu[row * 36 + wq * 4 + 0] = packh2(v.x, v.x);
        ghu[row * 36 + wq * 4 + 1] = packh2(v.y, v.y);
        ghu[row * 36 + wq * 4 + 2] = packh2(v.z, v.z);
        ghu[row * 36 + wq * 4 + 3] = packh2(v.w, v.w);
    }

    // ---- x tile source (pre-converted fp16x2) ----
    const char* xtile = reinterpret_cast<const char*>(
        g_xh + (size_t)tblk * (16 * 2048));   // per dc: 8192 bytes

    // cp.async stage of one dc chunk into buffer `ba` (all 128 threads)
    auto stageX = [&](int dc, uint32_t ba) {
        const char* src = xtile + (size_t)dc * 8192;
        #pragma unroll
        for (int k = 0; k < 4; k++) {
            int id = tid + 128 * k;       // 512 chunks of 16B
            int row = id >> 2, c = id & 3;
            CPA16(ba + (uint32_t)row * 80u + (uint32_t)c * 16u,
                  src + (size_t)row * 64 + c * 16);
        }
        CP_COMMIT();
    };

    // ---- B stream: linear chunk order [dc][ks2][e], 1024 chunks ----
    const uint32_t* pB = g_wt2h + (size_t)fblk * (16 * 2 * 32 * 1024)
                       + (wn * 128 + lane) * 4;
    uint4 bc0, bc1, bc2, bc3, bn0, bn1, bn2, bn3;
    LDB4(bc0, bc1, bc2, bc3, pB);   // chunk 0
    pB += 1024;

    float acc[4][8][4];
    #pragma unroll
    for (int i = 0; i < 4; i++)
        #pragma unroll
        for (int j = 0; j < 8; j++)
            #pragma unroll
            for (int q = 0; q < 4; q++) acc[i][j][q] = 0.f;

    uint32_t xh[4][4];
    uint32_t gA = ghA_base + (uint32_t)(wm * 64 + gid) * 144u;

    stageX(0, xcA0);   // prologue: dc 0 in flight

    #pragma unroll 1
    for (int dc = 0; dc < 16; dc++) {
        __syncthreads();   // all warps done with buffer being overwritten next
        if (dc + 1 < 16) stageX(dc + 1, (dc + 1) & 1 ? xcA1 : xcA0);
        if (dc + 1 < 16) { CP_WAIT1(); } else { CP_WAIT0(); }
        __syncthreads();   // dc's x tile visible to all warps
        uint32_t xcur = (dc & 1) ? xcA1 : xcA0;

        #pragma unroll 1
        for (int ks2 = 0; ks2 < 2; ks2++) {
            // hoisted x-fragment loads (conflict-free banks)
            #pragma unroll
            for (int i = 0; i < 4; i++) {
                uint32_t base = xcur
                    + ((uint32_t)(wm * 64 + 16 * i + gid) * 20u
                       + (uint32_t)(ks2 * 8 + tig)) * 4u;
                asm("ld.shared.b32 %0, [%1];" : "=r"(xh[i][0]) : "r"(base));
                asm("ld.shared.b32 %0, [%1];" : "=r"(xh[i][1]) : "r"(base + 8u*20u*4u));
                asm("ld.shared.b32 %0, [%1];" : "=r"(xh[i][2]) : "r"(base + 16u));
                asm("ld.shared.b32 %0, [%1];" : "=r"(xh[i][3]) : "r"(base + 8u*20u*4u + 16u));
            }

            // e-unrolled x2; final 1-chunk fetch overrun lands in the pad
            #pragma unroll 1
            for (int ep = 0; ep < 16; ep++) {
                uint32_t gpe[4][2][2];   // [i][row-half][u]
                #pragma unroll
                for (int i = 0; i < 4; i++) {
                    asm("ld.shared.v2.b32 {%0,%1}, [%2];"
                        : "=r"(gpe[i][0][0]), "=r"(gpe[i][0][1])
                        : "r"(gA + (uint32_t)(i * 2304) + (uint32_t)(ep * 8)));
                    asm("ld.shared.v2.b32 {%0,%1}, [%2];"
                        : "=r"(gpe[i][1][0]), "=r"(gpe[i][1][1])
                        : "r"(gA + (uint32_t)(i * 2304 + 1152) + (uint32_t)(ep * 8)));
                }
                // e = 2*ep: fetch next into bn*, consume bc*
                LDB4(bn0, bn1, bn2, bn3, pB); pB += 1024;
                MMABLOCK_R(0, bc0, bc1, bc2, bc3);
                // e = 2*ep+1: fetch next into bc*, consume bn*
                LDB4(bc0, bc1, bc2, bc3, pB); pB += 1024;
                MMABLOCK_R(1, bn0, bn1, bn2, bn3);
            }
        }
    }

    // ---- epilogue ----
    #pragma unroll
    for (int i = 0; i < 4; i++) {
        int row = t0 + wm * 64 + 16 * i + gid;
        #pragma unroll
        for (int j = 0; j < 8; j++) {
            int col = f0 + wn * 64 + 8 * j + 2 * tig;
            *reinterpret_cast<float2*>(out + (size_t)row * DDIM + col) =
                make_float2(acc[i][j][0], acc[i][j][1]);
            *reinterpret_cast<float2*>(out + (size_t)(row + 8) * DDIM + col) =
                make_float2(acc[i][j][2], acc[i][j][3]);
        }
    }
}

// ======================== launch ========================
extern "C" void kernel_launch(void* const* d_in, const int* in_sizes, int n_in,
                              void* d_out, int out_size) {
    const float* x  = (const float*)d_in[0];   // [8192, 512]
    const float* gw = (const float*)d_in[1];   // [512, 32]
    const float* gb = (const float*)d_in[2];   // [32]
    const float* ew = (const float*)d_in[3];   // [32, 512, 512]
    float* out = (float*)d_out;                // [8192, 512]

    cudaFuncSetAttribute(prep_gate_kernel,
                         cudaFuncAttributeMaxDynamicSharedMemorySize, PRE_SMEM);
    cudaFuncSetAttribute(moe_main_kernel,
                         cudaFuncAttributeMaxDynamicSharedMemorySize, MAIN_SMEM);

    prep_gate_kernel<<<704, 256, PRE_SMEM>>>(ew, x, gw, gb);

    dim3 grid(4, 64);
    moe_main_kernel<<<grid, 128, MAIN_SMEM>>>(out);
}